// round 1
// baseline (speedup 1.0000x reference)
#include <cuda_runtime.h>
#include <math.h>

// Problem constants
#define B   256
#define L   512
#define I   32
#define H   16
#define G   64            // 4*H gates
#define NT  511           // number of increments
#define SIGD 4368         // H + H^2 + H^3
#define O   10

// Scratch (device globals; no allocation allowed)
static __device__ float g_xw[B * L * G];        // 33.5 MB : input projection + biases
static __device__ float g_d [B * NT * H];       // 8.4 MB  : h increments d_t = h_{t+1}-h_t
static __device__ float g_sig[B * SIGD];        // 4.5 MB  : signatures

// ---------------------------------------------------------------------------
// Fast, accurate-enough activations (err ~1e-6 over the relevant range)
// ---------------------------------------------------------------------------
__device__ __forceinline__ float sigmoidf_(float x) {
    return __fdividef(1.f, 1.f + __expf(-x));
}
__device__ __forceinline__ float tanhf_(float x) {
    float e = __expf(-2.f * fabsf(x));
    float r = __fdividef(1.f - e, 1.f + e);
    return copysignf(r, x);
}

// ---------------------------------------------------------------------------
// K1: xw[bt][g] = b_ih[g] + b_hh[g] + sum_i X[bt][i] * W_ih[g][i]
// 64 bt-rows x 64 gates per 256-thread block; shared-tiled, 16 outputs/thread.
// ---------------------------------------------------------------------------
__global__ void __launch_bounds__(256) xw_kernel(const float* __restrict__ X,
                                                 const float* __restrict__ Wih,
                                                 const float* __restrict__ bih,
                                                 const float* __restrict__ bhh) {
    __shared__ float Xs[64 * 33];   // [bt_local][k], padded
    __shared__ float Ws[32 * 65];   // [k][g], padded (transposed W_ih)
    __shared__ float bs[64];

    int tid = threadIdx.x;
    int bt0 = blockIdx.x * 64;
    const float* Xg = X + (size_t)bt0 * I;

    for (int i = tid; i < 64 * I; i += 256) {
        int r = i >> 5, k = i & 31;
        Xs[r * 33 + k] = Xg[i];
        Ws[k * 65 + r] = Wih[i];     // Wih[g*32+k] with r=g here (same 2048-elem sweep)
    }
    if (tid < 64) bs[tid] = bih[tid] + bhh[tid];
    __syncthreads();

    int tg = tid & 15;        // gate quad: g = tg*4 + gi
    int tb = tid >> 4;        // bt quad:  bt_local = tb*4 + bi
    float acc[4][4];
#pragma unroll
    for (int bi = 0; bi < 4; bi++)
#pragma unroll
        for (int gi = 0; gi < 4; gi++)
            acc[bi][gi] = bs[tg * 4 + gi];

#pragma unroll 8
    for (int k = 0; k < I; k++) {
        float xv[4], wv[4];
#pragma unroll
        for (int bi = 0; bi < 4; bi++) xv[bi] = Xs[(tb * 4 + bi) * 33 + k];
#pragma unroll
        for (int gi = 0; gi < 4; gi++) wv[gi] = Ws[k * 65 + tg * 4 + gi];
#pragma unroll
        for (int bi = 0; bi < 4; bi++)
#pragma unroll
            for (int gi = 0; gi < 4; gi++)
                acc[bi][gi] = fmaf(xv[bi], wv[gi], acc[bi][gi]);
    }

#pragma unroll
    for (int bi = 0; bi < 4; bi++) {
        int bt = bt0 + tb * 4 + bi;
        float4 v = make_float4(acc[bi][0], acc[bi][1], acc[bi][2], acc[bi][3]);
        *reinterpret_cast<float4*>(g_xw + (size_t)bt * G + tg * 4) = v;
    }
}

// ---------------------------------------------------------------------------
// K2: LSTM recurrence. One warp per batch element.
// Lane l computes gate rows l and l+32 (so lanes<16: i,g ; lanes>=16: f,o).
// h (16 floats) replicated per lane; broadcast via shared each step.
// Writes increments d_t = h_{t+1} - h_t straight to g_d.
// ---------------------------------------------------------------------------
__global__ void __launch_bounds__(128) lstm_kernel(const float* __restrict__ Whh) {
    __shared__ __align__(16) float hsm[4][16];
    int lane = threadIdx.x & 31;
    int warp = threadIdx.x >> 5;
    int b = blockIdx.x * 4 + warp;

    float w0[H], w1[H];
#pragma unroll
    for (int j = 0; j < H; j++) {
        w0[j] = __ldg(Whh + lane * H + j);
        w1[j] = __ldg(Whh + (lane + 32) * H + j);
    }
    float h[H];
#pragma unroll
    for (int j = 0; j < H; j++) h[j] = 0.f;
    float c = 0.f, hprev = 0.f;

    const float* xp = g_xw + (size_t)b * (L * G) + lane;
    float* dp = g_d + (size_t)b * (NT * H);

    // prefetch first step's xw
    float x0 = xp[0], x1 = xp[32];

    for (int t = 0; t < L; t++) {
        // prefetch next step (independent of recurrence -> hides L2 latency)
        float nx0 = 0.f, nx1 = 0.f;
        if (t < L - 1) { nx0 = xp[(t + 1) * G]; nx1 = xp[(t + 1) * G + 32]; }

        float a0 = x0, a1 = x1, p0 = 0.f, p1 = 0.f;
#pragma unroll
        for (int j = 0; j < 8; j++) {
            a0 = fmaf(h[j],     w0[j],     a0);
            p0 = fmaf(h[j + 8], w0[j + 8], p0);
            a1 = fmaf(h[j],     w1[j],     a1);
            p1 = fmaf(h[j + 8], w1[j + 8], p1);
        }
        a0 += p0; a1 += p1;

        float fg = __shfl_down_sync(0xffffffffu, a0, 16);  // lanes<16 get f
        float og = __shfl_down_sync(0xffffffffu, a1, 16);  // lanes<16 get o

        float si = sigmoidf_(a0);
        float sf = sigmoidf_(fg);
        float so = sigmoidf_(og);
        float tg = tanhf_(a1);
        c = fmaf(sf, c, si * tg);
        float hn = so * tanhf_(c);

        if (lane < H) {
            hsm[warp][lane] = hn;
            if (t) dp[(t - 1) * H + lane] = hn - hprev;
            hprev = hn;
        }
        __syncwarp();
#pragma unroll
        for (int j = 0; j < H; j += 4) {
            float4 v = *reinterpret_cast<const float4*>(&hsm[warp][j]);
            h[j] = v.x; h[j + 1] = v.y; h[j + 2] = v.z; h[j + 3] = v.w;
        }
        __syncwarp();
        x0 = nx0; x1 = nx1;
    }
}

// ---------------------------------------------------------------------------
// K3: depth-3 signature scan. One 256-thread CTA per batch element.
// Thread tid = (a,b) owns S2[a][b] and S3[a][b][0..15].
// Rank-1 update: S3[a,b,c] += (S2 + d[a]d[b]/6 + S1[a]d[b]/2) * d[c]
// All increments preloaded to shared -> NO per-step __syncthreads.
// ---------------------------------------------------------------------------
__global__ void __launch_bounds__(256) sig_kernel() {
    __shared__ __align__(16) float ds[NT * H];   // 32704 B
    int bidx = blockIdx.x;
    int tid = threadIdx.x;

    const float4* s4 = reinterpret_cast<const float4*>(g_d + (size_t)bidx * (NT * H));
    float4* t4 = reinterpret_cast<float4*>(ds);
    for (int i = tid; i < (NT * H) / 4; i += 256) t4[i] = s4[i];
    __syncthreads();

    int a  = tid >> 4;
    int bb = tid & 15;

    float S1 = 0.f, S2 = 0.f;
    float S3[16];
#pragma unroll
    for (int cc = 0; cc < 16; cc++) S3[cc] = 0.f;

#pragma unroll 2
    for (int t = 0; t < NT; t++) {
        const float* dr = ds + t * H;
        float r[16];
#pragma unroll
        for (int j = 0; j < 16; j += 4) {
            float4 v = *reinterpret_cast<const float4*>(dr + j);
            r[j] = v.x; r[j + 1] = v.y; r[j + 2] = v.z; r[j + 3] = v.w;
        }
        float da = dr[a];
        float db = dr[bb];
        float m1 = da * db;
        float coef = fmaf(0.5f * S1, db, fmaf(m1, (1.f / 6.f), S2));
#pragma unroll
        for (int cc = 0; cc < 16; cc++) S3[cc] = fmaf(coef, r[cc], S3[cc]);
        S2 = fmaf(S1, db, fmaf(0.5f, m1, S2));
        S1 += da;
    }

    float* sb = g_sig + (size_t)bidx * SIGD;
    if (bb == 0) sb[a] = S1;            // level 1 (16 vals, one per distinct a)
    sb[H + tid] = S2;                    // level 2 flat a*16+b == tid
    float4* o4 = reinterpret_cast<float4*>(sb + H + H * H + tid * 16);
#pragma unroll
    for (int j = 0; j < 4; j++)
        o4[j] = make_float4(S3[j * 4], S3[j * 4 + 1], S3[j * 4 + 2], S3[j * 4 + 3]);
}

// ---------------------------------------------------------------------------
// K4: out[b][o] = sig[b] . fc_w[o] + fc_b[o]   (K=4368, O=10)
// ---------------------------------------------------------------------------
__global__ void __launch_bounds__(128) fc_kernel(const float* __restrict__ fcw,
                                                 const float* __restrict__ fcb,
                                                 float* __restrict__ out) {
    int bidx = blockIdx.x;
    int tid = threadIdx.x;
    int lane = tid & 31;
    int warp = tid >> 5;
    const float* sb = g_sig + (size_t)bidx * SIGD;

    float acc[O];
#pragma unroll
    for (int o = 0; o < O; o++) acc[o] = 0.f;

    for (int k = tid; k < SIGD; k += 128) {
        float s = sb[k];
#pragma unroll
        for (int o = 0; o < O; o++)
            acc[o] = fmaf(s, __ldg(fcw + (size_t)o * SIGD + k), acc[o]);
    }
#pragma unroll
    for (int off = 16; off > 0; off >>= 1)
#pragma unroll
        for (int o = 0; o < O; o++)
            acc[o] += __shfl_down_sync(0xffffffffu, acc[o], off);

    __shared__ float red[4][O];
    if (lane == 0)
#pragma unroll
        for (int o = 0; o < O; o++) red[warp][o] = acc[o];
    __syncthreads();
    if (tid < O) {
        float v = red[0][tid] + red[1][tid] + red[2][tid] + red[3][tid] + fcb[tid];
        out[bidx * O + tid] = v;
    }
}

// ---------------------------------------------------------------------------
extern "C" void kernel_launch(void* const* d_in, const int* in_sizes, int n_in,
                              void* d_out, int out_size) {
    const float* X   = (const float*)d_in[0];
    const float* Wih = (const float*)d_in[1];
    const float* Whh = (const float*)d_in[2];
    const float* bih = (const float*)d_in[3];
    const float* bhh = (const float*)d_in[4];
    const float* fcw = (const float*)d_in[5];
    const float* fcb = (const float*)d_in[6];
    float* out = (float*)d_out;

    xw_kernel<<<(B * L) / 64, 256>>>(X, Wih, bih, bhh);
    lstm_kernel<<<B / 4, 128>>>(Whh);
    sig_kernel<<<B, 256>>>();
    fc_kernel<<<B, 128>>>(fcw, fcb, out);
}

// round 2
// speedup vs baseline: 1.9967x; 1.9967x over previous
#include <cuda_runtime.h>
#include <math.h>

// Problem constants
#define B   256
#define L   512
#define I   32
#define H   16
#define G   64            // 4*H gates
#define NT  511           // number of increments
#define SIGD 4368         // H + H^2 + H^3
#define O   10

// Scratch (device globals; no allocation allowed)
static __device__ float g_xw[B * L * G];        // 33.5 MB : input projection + biases
static __device__ float g_d [B * NT * H];       // 8.4 MB  : h increments d_t = h_{t+1}-h_t

// ---------------------------------------------------------------------------
// Fast activations (ex2/rcp based, err ~1e-6)
// ---------------------------------------------------------------------------
__device__ __forceinline__ float sigmoidf_(float x) {
    return __fdividef(1.f, 1.f + __expf(-x));
}
__device__ __forceinline__ float tanhf_(float x) {
    float e = __expf(-2.f * fabsf(x));
    float r = __fdividef(1.f - e, 1.f + e);
    return copysignf(r, x);
}

// ---------------------------------------------------------------------------
// Packed fp32x2 helpers (Blackwell FFMA2 via PTX)
// ---------------------------------------------------------------------------
typedef unsigned long long u64t;
__device__ __forceinline__ u64t pack2_(float lo, float hi) {
    u64t r; asm("mov.b64 %0, {%1, %2};" : "=l"(r) : "f"(lo), "f"(hi)); return r;
}
__device__ __forceinline__ void unpack2_(u64t v, float& lo, float& hi) {
    asm("mov.b64 {%0, %1}, %2;" : "=f"(lo), "=f"(hi) : "l"(v));
}
__device__ __forceinline__ u64t ffma2_(u64t a, u64t b, u64t c) {
    u64t d; asm("fma.rn.f32x2 %0, %1, %2, %3;" : "=l"(d) : "l"(a), "l"(b), "l"(c));
    return d;
}

// ---------------------------------------------------------------------------
// K1: xw[bt][g] = b_ih[g] + b_hh[g] + sum_i X[bt][i] * W_ih[g][i]
// ---------------------------------------------------------------------------
__global__ void __launch_bounds__(256) xw_kernel(const float* __restrict__ X,
                                                 const float* __restrict__ Wih,
                                                 const float* __restrict__ bih,
                                                 const float* __restrict__ bhh) {
    __shared__ float Xs[64 * 33];
    __shared__ float Ws[32 * 65];
    __shared__ float bs[64];

    int tid = threadIdx.x;
    int bt0 = blockIdx.x * 64;
    const float* Xg = X + (size_t)bt0 * I;

    for (int i = tid; i < 64 * I; i += 256) {
        int r = i >> 5, k = i & 31;
        Xs[r * 33 + k] = Xg[i];
        Ws[k * 65 + r] = Wih[i];
    }
    if (tid < 64) bs[tid] = bih[tid] + bhh[tid];
    __syncthreads();

    int tg = tid & 15;
    int tb = tid >> 4;
    float acc[4][4];
#pragma unroll
    for (int bi = 0; bi < 4; bi++)
#pragma unroll
        for (int gi = 0; gi < 4; gi++)
            acc[bi][gi] = bs[tg * 4 + gi];

#pragma unroll 8
    for (int k = 0; k < I; k++) {
        float xv[4], wv[4];
#pragma unroll
        for (int bi = 0; bi < 4; bi++) xv[bi] = Xs[(tb * 4 + bi) * 33 + k];
#pragma unroll
        for (int gi = 0; gi < 4; gi++) wv[gi] = Ws[k * 65 + tg * 4 + gi];
#pragma unroll
        for (int bi = 0; bi < 4; bi++)
#pragma unroll
            for (int gi = 0; gi < 4; gi++)
                acc[bi][gi] = fmaf(xv[bi], wv[gi], acc[bi][gi]);
    }

#pragma unroll
    for (int bi = 0; bi < 4; bi++) {
        int bt = bt0 + tb * 4 + bi;
        float4 v = make_float4(acc[bi][0], acc[bi][1], acc[bi][2], acc[bi][3]);
        *reinterpret_cast<float4*>(g_xw + (size_t)bt * G + tg * 4) = v;
    }
}

// ---------------------------------------------------------------------------
// K2: LSTM recurrence. One warp per batch element.
// 4-deep register prefetch of xw; double-buffered h broadcast, 1 syncwarp/step.
// Writes increments d_t = h_{t+1} - h_t straight to g_d.
// ---------------------------------------------------------------------------
__global__ void __launch_bounds__(128) lstm_kernel(const float* __restrict__ Whh) {
    __shared__ __align__(16) float hsm[4][2][16];
    int lane = threadIdx.x & 31;
    int warp = threadIdx.x >> 5;
    int b = blockIdx.x * 4 + warp;

    float w0[H], w1[H];
#pragma unroll
    for (int j = 0; j < H; j++) {
        w0[j] = __ldg(Whh + lane * H + j);
        w1[j] = __ldg(Whh + (lane + 32) * H + j);
    }
    float h[H];
#pragma unroll
    for (int j = 0; j < H; j++) h[j] = 0.f;
    float c = 0.f, hprev = 0.f;

    const float* xp = g_xw + (size_t)b * (L * G) + lane;
    float* dp = g_d + (size_t)b * (NT * H);

    // 4-deep software prefetch pipeline
    float bx0[4], bx1[4];
#pragma unroll
    for (int k = 0; k < 4; k++) { bx0[k] = xp[k * G]; bx1[k] = xp[k * G + 32]; }

#pragma unroll 4
    for (int t = 0; t < L; t++) {
        int slot = t & 3;
        float a0 = bx0[slot], a1 = bx1[slot];
        if (t + 4 < L) { bx0[slot] = xp[(t + 4) * G]; bx1[slot] = xp[(t + 4) * G + 32]; }

        float q0 = 0.f, q1 = 0.f;
#pragma unroll
        for (int j = 0; j < 8; j++) {
            a0 = fmaf(h[j],     w0[j],     a0);
            q0 = fmaf(h[j + 8], w0[j + 8], q0);
            a1 = fmaf(h[j],     w1[j],     a1);
            q1 = fmaf(h[j + 8], w1[j + 8], q1);
        }
        a0 += q0; a1 += q1;

        float fg = __shfl_down_sync(0xffffffffu, a0, 16);  // lanes<16: f preact
        float og = __shfl_down_sync(0xffffffffu, a1, 16);  // lanes<16: o preact

        float si = sigmoidf_(a0);
        float sf = sigmoidf_(fg);
        float so = sigmoidf_(og);
        float tg = tanhf_(a1);
        c = fmaf(sf, c, si * tg);
        float hn = so * tanhf_(c);

        int buf = t & 1;
        if (lane < H) {
            hsm[warp][buf][lane] = hn;
            if (t) dp[(t - 1) * H + lane] = hn - hprev;
            hprev = hn;
        }
        __syncwarp();
#pragma unroll
        for (int j = 0; j < H; j += 4) {
            float4 v = *reinterpret_cast<const float4*>(&hsm[warp][buf][j]);
            h[j] = v.x; h[j + 1] = v.y; h[j + 2] = v.z; h[j + 3] = v.w;
        }
    }
}

// ---------------------------------------------------------------------------
// K3: depth-3 signature scan + fused FC epilogue. One 256-thread CTA / batch.
// Thread tid = (a,b): S2[a][b] scalar, S3[a][b][0..15] as 8 packed f32x2.
// Rank-1 update: S3[a,b,:] += (S2 + S1*d[b]/2 + d[a]d[b]/6) * d[:]
// No per-step syncs; increments preloaded to shared (broadcast LDS).
// ---------------------------------------------------------------------------
__global__ void __launch_bounds__(256) sig_kernel(const float* __restrict__ fcw,
                                                  const float* __restrict__ fcb,
                                                  float* __restrict__ out) {
    __shared__ __align__(16) float ds[NT * H];   // 32704 B
    __shared__ float red[8][O];
    int bidx = blockIdx.x;
    int tid = threadIdx.x;

    {
        const float4* s4 = reinterpret_cast<const float4*>(g_d + (size_t)bidx * (NT * H));
        float4* t4 = reinterpret_cast<float4*>(ds);
        for (int i = tid; i < (NT * H) / 4; i += 256) t4[i] = s4[i];
    }
    __syncthreads();

    int a  = tid >> 4;
    int bb = tid & 15;

    float S1h = 0.f, S2 = 0.f;       // S1h = S1/2 (exact scaling)
    u64t S3p[8];
#pragma unroll
    for (int j = 0; j < 8; j++) S3p[j] = 0ull;

#pragma unroll 2
    for (int t = 0; t < NT; t++) {
        const float* dr = ds + t * H;
        float4 v0 = *reinterpret_cast<const float4*>(dr);
        float4 v1 = *reinterpret_cast<const float4*>(dr + 4);
        float4 v2 = *reinterpret_cast<const float4*>(dr + 8);
        float4 v3 = *reinterpret_cast<const float4*>(dr + 12);
        float da = dr[a];
        float db = dr[bb];

        float m1   = da * db;
        float db2  = db + db;
        float coef = fmaf(S1h, db, fmaf(m1, (1.f / 6.f), S2));
        u64t cp = pack2_(coef, coef);

        S3p[0] = ffma2_(cp, pack2_(v0.x, v0.y), S3p[0]);
        S3p[1] = ffma2_(cp, pack2_(v0.z, v0.w), S3p[1]);
        S3p[2] = ffma2_(cp, pack2_(v1.x, v1.y), S3p[2]);
        S3p[3] = ffma2_(cp, pack2_(v1.z, v1.w), S3p[3]);
        S3p[4] = ffma2_(cp, pack2_(v2.x, v2.y), S3p[4]);
        S3p[5] = ffma2_(cp, pack2_(v2.z, v2.w), S3p[5]);
        S3p[6] = ffma2_(cp, pack2_(v3.x, v3.y), S3p[6]);
        S3p[7] = ffma2_(cp, pack2_(v3.z, v3.w), S3p[7]);

        S2  = fmaf(S1h, db2, fmaf(0.5f, m1, S2));
        S1h = fmaf(0.5f, da, S1h);
    }

    // ---- fused FC: out[b][o] = sig . fc_w[o] + fc_b[o] ----
    float S3[16];
#pragma unroll
    for (int j = 0; j < 8; j++) unpack2_(S3p[j], S3[2 * j], S3[2 * j + 1]);
    float S1 = S1h + S1h;

    float part[O];
#pragma unroll
    for (int o = 0; o < O; o++) {
        const float* wr = fcw + (size_t)o * SIGD;
        float acc = S2 * __ldg(wr + H + tid);              // level-2 term
        if (bb == 0) acc = fmaf(S1, __ldg(wr + a), acc);   // level-1 term
        const float4* w4 = reinterpret_cast<const float4*>(wr + H + H * H + tid * 16);
#pragma unroll
        for (int j = 0; j < 4; j++) {
            float4 w = __ldg(w4 + j);
            acc = fmaf(S3[4 * j + 0], w.x, acc);
            acc = fmaf(S3[4 * j + 1], w.y, acc);
            acc = fmaf(S3[4 * j + 2], w.z, acc);
            acc = fmaf(S3[4 * j + 3], w.w, acc);
        }
        part[o] = acc;
    }

    int lane = tid & 31, warp = tid >> 5;
#pragma unroll
    for (int off = 16; off > 0; off >>= 1)
#pragma unroll
        for (int o = 0; o < O; o++)
            part[o] += __shfl_down_sync(0xffffffffu, part[o], off);
    if (lane == 0)
#pragma unroll
        for (int o = 0; o < O; o++) red[warp][o] = part[o];
    __syncthreads();

    if (tid < O) {
        float v = fcb[tid];
#pragma unroll
        for (int w = 0; w < 8; w++) v += red[w][tid];
        out[bidx * O + tid] = v;
    }
}

// ---------------------------------------------------------------------------
extern "C" void kernel_launch(void* const* d_in, const int* in_sizes, int n_in,
                              void* d_out, int out_size) {
    const float* X   = (const float*)d_in[0];
    const float* Wih = (const float*)d_in[1];
    const float* Whh = (const float*)d_in[2];
    const float* bih = (const float*)d_in[3];
    const float* bhh = (const float*)d_in[4];
    const float* fcw = (const float*)d_in[5];
    const float* fcb = (const float*)d_in[6];
    float* out = (float*)d_out;

    xw_kernel<<<(B * L) / 64, 256>>>(X, Wih, bih, bhh);
    lstm_kernel<<<B / 4, 128>>>(Whh);
    sig_kernel<<<B, 256>>>(fcw, fcb, out);
}